// round 11
// baseline (speedup 1.0000x reference)
#include <cuda_runtime.h>
#include <cuda_bf16.h>
#include <cstdint>

#define BB 4
#define NN 20000
#define HH 448
#define WW 448
#define HWSZ (HH*WW)          // 200704
#define PTS (2*BB*NN)         // 160000 point-instances per role
#define GRPS (PTS/4)          // 40000 groups of 4 points, 1 warp each
#define LUTB 392              // (2*BB*HWSZ)/4 / 1024 int4-clear blocks

// ---------------- device scratch (static globals; no runtime alloc) -------------
__device__ __align__(16) float g_q[(size_t)PTS*32];
__device__ __align__(16) float g_k[(size_t)PTS*32];
__device__ __align__(16) float g_v[(size_t)PTS*32];
__device__ __align__(16) float g_o[(size_t)PTS*32];   // compact attention output
__device__ float g_sinv[(size_t)PTS*2];
__device__ __align__(16) int   g_lut[2*BB*HWSZ];

// [dir][m][in_ch][out_ch]; m: 0=q 1=k 2=v 3=out  (lane = out channel -> coalesced)
__device__ __align__(16) float g_W[2][4][32][32];
__device__ float g_bq[2][32], g_bkv[2][32], g_bkinv[2][32];
__device__ float g_bv0[2][32], g_bvinv[2][32], g_bo[2][32];
__device__ __align__(16) float g_pv[2][9][32];

__constant__ int c_sh[9][2] = {{0,0},{-1,0},{1,0},{0,1},{-1,1},{1,1},{0,-1},{-1,-1},{1,-1}};

// ---------------- K0: zero the output canvas (no dependencies; forked stream) ----
__global__ void k_zero(float4* __restrict__ out4, int n4)
{
    int i = blockIdx.x * blockDim.x + threadIdx.x;
    if (i < n4) out4[i] = make_float4(0.f, 0.f, 0.f, 0.f);
}

// ---------------- K1: LUT clear + fold weight chains (merged init) ---------------
__global__ void k_init(const float* qw1, const float* qb1,
                       const float* qw2, const float* qb2,
                       const float* posw, const float* posb,
                       const float* iw1, const float* ib1, const float* ow1, const float* ob1,
                       const float* iw2, const float* ib2, const float* ow2, const float* ob2)
{
    if (blockIdx.x < LUTB) {
        int i = blockIdx.x * 1024 + threadIdx.x;
        ((int4*)g_lut)[i] = make_int4(-1, -1, -1, -1);
        return;
    }
    int b2 = blockIdx.x - LUTB;   // 0..7
    int d = b2 >> 2;              // direction
    int m = b2 & 3;               // 0..3
    int t = threadIdx.x;
    const float* qkvw = d ? qw2 : qw1;
    const float* qkvb = d ? qb2 : qb1;
    const float* iw   = d ? iw2 : iw1;
    const float* ib   = d ? ib2 : ib1;
    const float* ow   = d ? ow2 : ow1;
    const float* ob   = d ? ob2 : ob1;

    int i = t >> 5, j = t & 31;   // i = out channel, j = in channel
    if (m < 3) {
        float acc = 0.f;
        #pragma unroll
        for (int c = 0; c < 32; c++)
            acc = fmaf(iw[(m*32+i)*32 + c], qkvw[(m*32+c)*32 + j], acc);
        g_W[d][m][j][i] = acc;
    } else {
        g_W[d][3][j][i] = ow[i*32 + j];   // store [in][out]
        if (t < 32) {
            int i2 = t;
            float aq = ib[i2], ak = ib[32+i2], av = ib[64+i2];
            #pragma unroll
            for (int c = 0; c < 32; c++) {
                aq = fmaf(iw[i2*32 + c],        qkvb[c],      aq);
                ak = fmaf(iw[(32+i2)*32 + c],   qkvb[32+c],   ak);
                av = fmaf(iw[(64+i2)*32 + c],   qkvb[64+c],   av);
            }
            g_bq[d][i2]    = aq;
            g_bkv[d][i2]   = ak;
            g_bkinv[d][i2] = ib[32+i2];
            g_bv0[d][i2]   = av;
            g_bvinv[d][i2] = ib[64+i2];
            g_bo[d][i2]    = ob[i2];
        } else if (t < 32 + 9*32) {
            int s = (t - 32) >> 5, i2 = t & 31;
            float acc = 0.f;
            #pragma unroll
            for (int c = 0; c < 32; c++) {
                float pc = (float)c_sh[s][0]*posw[2*c] + (float)c_sh[s][1]*posw[2*c+1] + posb[c];
                acc = fmaf(iw[(64+i2)*32 + c], pc, acc);
            }
            g_pv[d][s][i2] = acc;
        }
    }
}

// ---------------- K3: layernorm + projections, 4 points per warp -----------------
__global__ void k_pre(const float* __restrict__ li_f, const float* __restrict__ ra_f,
                      const int* __restrict__ li_c, const int* __restrict__ ra_c,
                      const float* __restrict__ li_nw, const float* __restrict__ li_nb,
                      const float* __restrict__ ra_nw, const float* __restrict__ ra_nb)
{
    __shared__ float4 sb4[8][32];       // [wid][chan] -> 4 points per float4
    int lane = threadIdx.x & 31, wid = threadIdx.x >> 5;
    int grp = blockIdx.x * 8 + wid;
    if (grp >= GRPS) return;
    int set = grp / (GRPS/2);                 // 0..1
    int rem = grp - set * (GRPS/2);           // 0..19999
    int b = rem / (NN/4);
    int j0 = (rem - b * (NN/4)) * 4;

    const float* feat = (set ? ra_f : li_f) + (size_t)(b*NN + j0) * 32;
    float nw = (set ? ra_nw : li_nw)[lane];
    float nbv = (set ? ra_nb : li_nb)[lane];

    // front-batched loads (MLP=4)
    float x[4];
    #pragma unroll
    for (int p = 0; p < 4; p++) x[p] = feat[p*32 + lane];

    float* sbf = (float*)&sb4[wid][lane];
    #pragma unroll
    for (int p = 0; p < 4; p++) {
        float s = x[p];
        #pragma unroll
        for (int o = 16; o; o >>= 1) s += __shfl_xor_sync(~0u, s, o);
        float mu = s * (1.f/32.f);
        float dx = x[p] - mu;
        float vv = dx * dx;
        #pragma unroll
        for (int o = 16; o; o >>= 1) vv += __shfl_xor_sync(~0u, vv, o);
        sbf[p] = dx * rsqrtf(vv * (1.f/32.f) + 1e-5f) * nw + nbv;
    }
    __syncwarp();

    int dq = set, dk = set ^ 1;
    float aq[4], ak[4], av[4];
    float bqv = g_bq[dq][lane], bkv = g_bkv[dk][lane], bvv = g_bv0[dk][lane];
    #pragma unroll
    for (int p = 0; p < 4; p++) { aq[p] = bqv; ak[p] = bkv; av[p] = bvv; }

    #pragma unroll 4
    for (int c = 0; c < 32; c++) {
        float wq = g_W[dq][0][c][lane];
        float wk = g_W[dk][1][c][lane];
        float wv = g_W[dk][2][c][lane];
        float4 f = sb4[wid][c];         // one LDS.128, broadcast
        aq[0] = fmaf(f.x, wq, aq[0]); aq[1] = fmaf(f.y, wq, aq[1]);
        aq[2] = fmaf(f.z, wq, aq[2]); aq[3] = fmaf(f.w, wq, aq[3]);
        ak[0] = fmaf(f.x, wk, ak[0]); ak[1] = fmaf(f.y, wk, ak[1]);
        ak[2] = fmaf(f.z, wk, ak[2]); ak[3] = fmaf(f.w, wk, ak[3]);
        av[0] = fmaf(f.x, wv, av[0]); av[1] = fmaf(f.y, wv, av[1]);
        av[2] = fmaf(f.z, wv, av[2]); av[3] = fmaf(f.w, wv, av[3]);
    }

    size_t pq = ((size_t)(dq*BB + b) * NN + j0);
    size_t pk = ((size_t)(dk*BB + b) * NN + j0);
    float bki = g_bkinv[dq][lane];
    #pragma unroll
    for (int p = 0; p < 4; p++) {
        g_q[(pq+p)*32 + lane] = aq[p];
        g_k[(pk+p)*32 + lane] = ak[p];
        g_v[(pk+p)*32 + lane] = av[p];
        // invalid-neighbor score: dot(q, bk_inv)/4 per head
        float pr = aq[p] * bki;
        pr += __shfl_xor_sync(~0u, pr, 8);
        pr += __shfl_xor_sync(~0u, pr, 4);
        pr += __shfl_xor_sync(~0u, pr, 2);
        pr += __shfl_xor_sync(~0u, pr, 1);
        if ((lane & 15) == 0) g_sinv[(pq+p)*2 + (lane >> 4)] = pr * 0.25f;
    }

    if (lane < 4) {
        const int* cc = (set ? ra_c : li_c) + (size_t)(b*NN + j0 + lane) * 2;
        int h = __ldg(&cc[0]), w = __ldg(&cc[1]);
        g_lut[(dk*BB + b) * HWSZ + h*WW + w] = j0 + lane;
    }
}

// ---------------- K4: sparse attention, 4 points per warp ------------------------
__global__ void k_attn(const int* __restrict__ li_c, const int* __restrict__ ra_c)
{
    __shared__ float4 sb4[8][32];
    int lane = threadIdx.x & 31, wid = threadIdx.x >> 5;
    int grp = blockIdx.x * 8 + wid;
    if (grp >= GRPS) return;
    int d = grp / (GRPS/2);
    int rem = grp - d * (GRPS/2);
    int b = rem / (NN/4);
    int j0 = (rem - b * (NN/4)) * 4;

    size_t base = (size_t)(d*BB + b) * NN + j0;     // q / o / sinv rows
    size_t kvbase = (size_t)(d*BB + b) * NN;        // kv pool (other modality)
    const int* lut = g_lut + (d*BB + b) * HWSZ;

    // coords for the 4 query points: lanes 0..7 load 8 ints, broadcast later
    const int* qc = (d == 0 ? li_c : ra_c) + (size_t)(b*NN + j0) * 2;
    int craw = (lane < 8) ? __ldg(&qc[lane]) : 0;

    int head = lane >> 4;

    // front-batched independent loads (MLP=8)
    float qv[4], siv[4];
    #pragma unroll
    for (int p = 0; p < 4; p++) qv[p] = g_q[(base+p)*32 + lane];
    #pragma unroll
    for (int p = 0; p < 4; p++) siv[p] = g_sinv[(base+p)*2 + head];

    float bvi = g_bvinv[d][lane];
    int sh_dh = (lane < 9) ? c_sh[lane][0] : 0;
    int sh_dw = (lane < 9) ? c_sh[lane][1] : 0;

    float* sbf = (float*)&sb4[wid][lane];
    #pragma unroll
    for (int p = 0; p < 4; p++) {
        int h = __shfl_sync(~0u, craw, 2*p);
        int w = __shfl_sync(~0u, craw, 2*p + 1);

        // lane-parallel probe: lane s<9 checks shift s
        int idx = -1;
        if (lane < 9) {
            int sh = h + sh_dh, sw = w + sh_dw;
            if ((unsigned)sh < (unsigned)HH && (unsigned)sw < (unsigned)WW)
                idx = __ldg(&lut[sh*WW + sw]);
        }
        unsigned vm = __ballot_sync(~0u, idx >= 0);
        int nval = __popc(vm);

        // online softmax seeded with invalid class (9-nval copies of score sinv)
        float m_run = siv[p];
        float ssum = (float)(9 - nval);
        float o = ssum * bvi;

        unsigned mm = vm;
        while (mm) {
            int s = __ffs(mm) - 1; mm &= mm - 1;
            int id = __shfl_sync(~0u, idx, s);
            size_t off = (kvbase + id) * 32 + lane;
            float kc = g_k[off];
            float pr = qv[p] * kc;
            pr += __shfl_xor_sync(~0u, pr, 8);
            pr += __shfl_xor_sync(~0u, pr, 4);
            pr += __shfl_xor_sync(~0u, pr, 2);
            pr += __shfl_xor_sync(~0u, pr, 1);
            pr *= 0.25f;
            float vval = g_v[off] + g_pv[d][s][lane];
            float mnew = fmaxf(m_run, pr);
            float corr = __expf(m_run - mnew);
            float wgt  = __expf(pr - mnew);
            ssum = ssum * corr + wgt;
            o = fmaf(o, corr, wgt * vval);
            m_run = mnew;
        }
        sbf[p] = o / ssum;
    }
    __syncwarp();

    // out-projection, weights + LDS.128 reused across 4 points
    float acc[4];
    float bo = g_bo[d][lane];
    #pragma unroll
    for (int p = 0; p < 4; p++) acc[p] = bo;
    #pragma unroll 4
    for (int c = 0; c < 32; c++) {
        float wo = g_W[d][3][c][lane];
        float4 f = sb4[wid][c];         // one LDS.128, broadcast
        acc[0] = fmaf(f.x, wo, acc[0]);
        acc[1] = fmaf(f.y, wo, acc[1]);
        acc[2] = fmaf(f.z, wo, acc[2]);
        acc[3] = fmaf(f.w, wo, acc[3]);
    }
    #pragma unroll
    for (int p = 0; p < 4; p++)
        g_o[(base+p)*32 + lane] = acc[p];
}

// ---------------- K5: point-major sparse scatter (only occupied pixels) ----------
// Warp per 4 points. Lane = channel. No LUT reads; canvas already zeroed by k_zero.
__global__ void k_spts(const int* __restrict__ li_c, const int* __restrict__ ra_c,
                       float* __restrict__ out)
{
    int lane = threadIdx.x & 31, wid = threadIdx.x >> 5;
    int grp = blockIdx.x * 8 + wid;
    if (grp >= GRPS) return;
    int d = grp / (GRPS/2);
    int rem = grp - d * (GRPS/2);
    int b = rem / (NN/4);
    int j0 = (rem - b * (NN/4)) * 4;

    size_t base = (size_t)(d*BB + b) * NN + j0;
    const int* qc = (d == 0 ? li_c : ra_c) + (size_t)(b*NN + j0) * 2;
    int craw = (lane < 8) ? __ldg(&qc[lane]) : 0;

    // front-batched value loads (MLP=4)
    float val[4];
    #pragma unroll
    for (int p = 0; p < 4; p++) val[p] = g_o[(base+p)*32 + lane];

    float* dst = out + ((size_t)(d*BB + b) * 32 + lane) * HWSZ;
    #pragma unroll
    for (int p = 0; p < 4; p++) {
        int h = __shfl_sync(~0u, craw, 2*p);
        int w = __shfl_sync(~0u, craw, 2*p + 1);
        dst[h*WW + w] = val[p];
    }
}

// --------------------------------- launch ---------------------------------------
extern "C" void kernel_launch(void* const* d_in, const int* in_sizes, int n_in,
                              void* d_out, int out_size)
{
    const float* li_f  = (const float*)d_in[0];
    const float* ra_f  = (const float*)d_in[1];
    const int*   li_c  = (const int*)d_in[2];
    const int*   ra_c  = (const int*)d_in[3];
    const float* li_nw = (const float*)d_in[4];
    const float* li_nb = (const float*)d_in[5];
    const float* ra_nw = (const float*)d_in[6];
    const float* ra_nb = (const float*)d_in[7];
    const float* qw1   = (const float*)d_in[8];
    const float* qb1   = (const float*)d_in[9];
    const float* qw2   = (const float*)d_in[10];
    const float* qb2   = (const float*)d_in[11];
    const float* posw  = (const float*)d_in[12];
    const float* posb  = (const float*)d_in[13];
    const float* iw1   = (const float*)d_in[14];
    const float* ib1   = (const float*)d_in[15];
    const float* ow1   = (const float*)d_in[16];
    const float* ob1   = (const float*)d_in[17];
    const float* iw2   = (const float*)d_in[18];
    const float* ib2   = (const float*)d_in[19];
    const float* ow2   = (const float*)d_in[20];
    const float* ob2   = (const float*)d_in[21];

    // lazy one-time creation of the side stream + fork/join events (host-side
    // resources only; identical GPU work every call)
    static cudaStream_t s_zero = nullptr;
    static cudaEvent_t  ev_fork = nullptr, ev_zero = nullptr;
    if (!s_zero) {
        cudaStreamCreateWithFlags(&s_zero, cudaStreamNonBlocking);
        cudaEventCreateWithFlags(&ev_fork, cudaEventDisableTiming);
        cudaEventCreateWithFlags(&ev_zero, cudaEventDisableTiming);
    }

    // fork: canvas zero runs concurrently with the compute chain
    cudaEventRecord(ev_fork, 0);
    cudaStreamWaitEvent(s_zero, ev_fork, 0);
    int n4 = out_size / 4;
    k_zero<<<(n4 + 255)/256, 256, 0, s_zero>>>((float4*)d_out, n4);
    cudaEventRecord(ev_zero, s_zero);

    // compute chain on the main (capture) stream
    k_init<<<LUTB + 8, 1024>>>(qw1, qb1, qw2, qb2, posw, posb,
                               iw1, ib1, ow1, ob1, iw2, ib2, ow2, ob2);

    k_pre<<<(GRPS + 7)/8, 256>>>(li_f, ra_f, li_c, ra_c, li_nw, li_nb, ra_nw, ra_nb);

    k_attn<<<(GRPS + 7)/8, 256>>>(li_c, ra_c);

    // join: sparse writes must land after the zero pass
    cudaStreamWaitEvent(0, ev_zero, 0);
    k_spts<<<(GRPS + 7)/8, 256>>>(li_c, ra_c, (float*)d_out);
}

// round 12
// speedup vs baseline: 1.6231x; 1.6231x over previous
#include <cuda_runtime.h>
#include <cuda_bf16.h>
#include <cstdint>

#define BB 4
#define NN 20000
#define HH 448
#define WW 448
#define HWSZ (HH*WW)          // 200704
#define PTS (2*BB*NN)         // 160000 point-instances per role
#define GRPS (PTS/4)          // 40000 groups of 4 points
#define GRPD (GRPS/2)         // 20000 groups per direction
#define LUTB 392              // (2*BB*HWSZ)/4 / 1024 int4-clear blocks

// ---------------- device scratch (static globals; no runtime alloc) -------------
__device__ __align__(16) float  g_q[(size_t)PTS*32];
__device__ __align__(16) float  g_k[(size_t)PTS*32];
__device__ __align__(16) float2 g_u[(size_t)PTS*32];   // Wo-folded V, both heads
__device__ __align__(16) float  g_o[(size_t)PTS*32];   // final per-point output
__device__ float g_sinv[(size_t)PTS*2];
__device__ __align__(16) int   g_lut[2*BB*HWSZ];

// weights, [in][out] so lane = out channel -> broadcast LDG
__device__ __align__(16) float g_Wq[2][32][32];
__device__ __align__(16) float g_Wk[2][32][32];
__device__ __align__(16) float g_Wu[2][32][32][2];     // folded Wo_h@Wv_eff_h, [c][lane][h]
__device__ float g_bq[2][32], g_bkv[2][32], g_bkinv[2][32], g_bo[2][32];
__device__ __align__(8) float g_bu[2][32][2];          // Wo_h@bv0_h
__device__ __align__(8) float g_uinv[2][32][2];        // Wo_h@bvinv_h
__device__ __align__(8) float g_pu[2][9][32][2];       // Wo_h@pv_s_h

__constant__ int c_sh[9][2] = {{0,0},{-1,0},{1,0},{0,1},{-1,1},{1,1},{0,-1},{-1,-1},{1,-1}};

// ---------------- K1: LUT clear + fold weight chains (merged init) ---------------
__global__ void k_init(const float* qw1, const float* qb1,
                       const float* qw2, const float* qb2,
                       const float* posw, const float* posb,
                       const float* iw1, const float* ib1, const float* ow1, const float* ob1,
                       const float* iw2, const float* ib2, const float* ow2, const float* ob2)
{
    if (blockIdx.x < LUTB) {
        int i = blockIdx.x * 1024 + threadIdx.x;
        ((int4*)g_lut)[i] = make_int4(-1, -1, -1, -1);
        return;
    }
    int b2 = blockIdx.x - LUTB;   // 0..7
    int d = b2 >> 2;              // direction
    int m = b2 & 3;               // 0..3
    int t = threadIdx.x;
    const float* qkvw = d ? qw2 : qw1;
    const float* qkvb = d ? qb2 : qb1;
    const float* iw   = d ? iw2 : iw1;
    const float* ib   = d ? ib2 : ib1;
    const float* ow   = d ? ow2 : ow1;
    const float* ob   = d ? ob2 : ob1;

    int i = t >> 5, j = t & 31;   // i = out channel, j = in channel

    if (m == 0 || m == 1) {
        float acc = 0.f;
        #pragma unroll
        for (int c = 0; c < 32; c++)
            acc = fmaf(iw[(m*32+i)*32 + c], qkvw[(m*32+c)*32 + j], acc);
        if (m == 0) g_Wq[d][j][i] = acc;
        else        g_Wk[d][j][i] = acc;
    } else if (m == 2) {
        // Wv_eff then U_h = Wo_h @ Wv_eff_h
        __shared__ float s_wv[32][32];
        float acc = 0.f;
        #pragma unroll
        for (int c = 0; c < 32; c++)
            acc = fmaf(iw[(64+i)*32 + c], qkvw[(64+c)*32 + j], acc);
        s_wv[i][j] = acc;
        __syncthreads();
        float u0 = 0.f, u1 = 0.f;
        #pragma unroll
        for (int c = 0; c < 16; c++) {
            u0 = fmaf(ow[i*32 + c],      s_wv[c][j],      u0);
            u1 = fmaf(ow[i*32 + 16 + c], s_wv[16 + c][j], u1);
        }
        g_Wu[d][j][i][0] = u0;
        g_Wu[d][j][i][1] = u1;
    } else {
        // biases, pos-folds, and their Wo-folds
        __shared__ float s_bv0[32];
        __shared__ float s_pv[9][32];
        if (t < 32) {
            int i2 = t;
            float aq = ib[i2], ak = ib[32+i2], av = ib[64+i2];
            #pragma unroll
            for (int c = 0; c < 32; c++) {
                aq = fmaf(iw[i2*32 + c],        qkvb[c],      aq);
                ak = fmaf(iw[(32+i2)*32 + c],   qkvb[32+c],   ak);
                av = fmaf(iw[(64+i2)*32 + c],   qkvb[64+c],   av);
            }
            g_bq[d][i2]    = aq;
            g_bkv[d][i2]   = ak;
            g_bkinv[d][i2] = ib[32+i2];
            g_bo[d][i2]    = ob[i2];
            s_bv0[i2]      = av;
        } else if (t < 32 + 9*32) {
            int s = (t - 32) >> 5, i2 = t & 31;
            float acc = 0.f;
            #pragma unroll
            for (int c = 0; c < 32; c++) {
                float pc = (float)c_sh[s][0]*posw[2*c] + (float)c_sh[s][1]*posw[2*c+1] + posb[c];
                acc = fmaf(iw[(64+i2)*32 + c], pc, acc);
            }
            s_pv[s][i2] = acc;
        }
        __syncthreads();
        if (t < 64) {
            int h = t >> 5, i2 = t & 31;
            float a = 0.f;
            #pragma unroll
            for (int c = 0; c < 16; c++)
                a = fmaf(ow[i2*32 + h*16 + c], s_bv0[h*16 + c], a);
            g_bu[d][i2][h] = a;
        } else if (t < 128) {
            int tt = t - 64, h = tt >> 5, i2 = tt & 31;
            float a = 0.f;
            #pragma unroll
            for (int c = 0; c < 16; c++)
                a = fmaf(ow[i2*32 + h*16 + c], ib[64 + h*16 + c], a);
            g_uinv[d][i2][h] = a;
        } else if (t < 128 + 9*64) {
            int tt = t - 128;
            int s = tt / 64, r = tt & 63, h = r >> 5, i2 = r & 31;
            float a = 0.f;
            #pragma unroll
            for (int c = 0; c < 16; c++)
                a = fmaf(ow[i2*32 + h*16 + c], s_pv[s][h*16 + c], a);
            g_pu[d][s][i2][h] = a;
        }
    }
}

// ---------------- K3: layernorm + q/k/u projections, 4 points per warp -----------
__global__ void k_pre(const float* __restrict__ li_f, const float* __restrict__ ra_f,
                      const int* __restrict__ li_c, const int* __restrict__ ra_c,
                      const float* __restrict__ li_nw, const float* __restrict__ li_nb,
                      const float* __restrict__ ra_nw, const float* __restrict__ ra_nb)
{
    __shared__ float4 sb4[8][32];       // [wid][chan] -> 4 points per float4
    int lane = threadIdx.x & 31, wid = threadIdx.x >> 5;
    int grp = blockIdx.x * 8 + wid;
    if (grp >= GRPS) return;
    int set = grp / GRPD;                     // 0..1
    int rem = grp - set * GRPD;               // 0..19999
    int b = rem / (NN/4);
    int j0 = (rem - b * (NN/4)) * 4;

    const float* feat = (set ? ra_f : li_f) + (size_t)(b*NN + j0) * 32;
    float nw = (set ? ra_nw : li_nw)[lane];
    float nbv = (set ? ra_nb : li_nb)[lane];

    // front-batched loads (MLP=4)
    float x[4];
    #pragma unroll
    for (int p = 0; p < 4; p++) x[p] = feat[p*32 + lane];

    float* sbf = (float*)&sb4[wid][lane];
    #pragma unroll
    for (int p = 0; p < 4; p++) {
        float s = x[p];
        #pragma unroll
        for (int o = 16; o; o >>= 1) s += __shfl_xor_sync(~0u, s, o);
        float mu = s * (1.f/32.f);
        float dx = x[p] - mu;
        float vv = dx * dx;
        #pragma unroll
        for (int o = 16; o; o >>= 1) vv += __shfl_xor_sync(~0u, vv, o);
        sbf[p] = dx * rsqrtf(vv * (1.f/32.f) + 1e-5f) * nw + nbv;
    }
    __syncwarp();

    int dq = set, dk = set ^ 1;
    float aq[4], ak[4], au0[4], au1[4];
    float bqv = g_bq[dq][lane], bkv = g_bkv[dk][lane];
    float bu0 = g_bu[dk][lane][0], bu1 = g_bu[dk][lane][1];
    #pragma unroll
    for (int p = 0; p < 4; p++) { aq[p]=bqv; ak[p]=bkv; au0[p]=bu0; au1[p]=bu1; }

    #pragma unroll 4
    for (int c = 0; c < 32; c++) {
        float wq = g_Wq[dq][c][lane];
        float wk = g_Wk[dk][c][lane];
        float2 wu = *(const float2*)&g_Wu[dk][c][lane][0];
        float4 f = sb4[wid][c];         // one LDS.128, broadcast
        aq[0]  = fmaf(f.x, wq, aq[0]);   aq[1]  = fmaf(f.y, wq, aq[1]);
        aq[2]  = fmaf(f.z, wq, aq[2]);   aq[3]  = fmaf(f.w, wq, aq[3]);
        ak[0]  = fmaf(f.x, wk, ak[0]);   ak[1]  = fmaf(f.y, wk, ak[1]);
        ak[2]  = fmaf(f.z, wk, ak[2]);   ak[3]  = fmaf(f.w, wk, ak[3]);
        au0[0] = fmaf(f.x, wu.x, au0[0]); au0[1] = fmaf(f.y, wu.x, au0[1]);
        au0[2] = fmaf(f.z, wu.x, au0[2]); au0[3] = fmaf(f.w, wu.x, au0[3]);
        au1[0] = fmaf(f.x, wu.y, au1[0]); au1[1] = fmaf(f.y, wu.y, au1[1]);
        au1[2] = fmaf(f.z, wu.y, au1[2]); au1[3] = fmaf(f.w, wu.y, au1[3]);
    }

    size_t pq = ((size_t)(dq*BB + b) * NN + j0);
    size_t pk = ((size_t)(dk*BB + b) * NN + j0);
    float bki = g_bkinv[dq][lane];
    #pragma unroll
    for (int p = 0; p < 4; p++) {
        g_q[(pq+p)*32 + lane] = aq[p];
        g_k[(pk+p)*32 + lane] = ak[p];
        g_u[(pk+p)*32 + lane] = make_float2(au0[p], au1[p]);
        // invalid-neighbor score: dot(q, bk_inv)/4 per head
        float pr = aq[p] * bki;
        pr += __shfl_xor_sync(~0u, pr, 8);
        pr += __shfl_xor_sync(~0u, pr, 4);
        pr += __shfl_xor_sync(~0u, pr, 2);
        pr += __shfl_xor_sync(~0u, pr, 1);
        if ((lane & 15) == 0) g_sinv[(pq+p)*2 + (lane >> 4)] = pr * 0.25f;
    }

    if (lane < 4) {
        const int* cc = (set ? ra_c : li_c) + (size_t)(b*NN + j0 + lane) * 2;
        int h = __ldg(&cc[0]), w = __ldg(&cc[1]);
        g_lut[(dk*BB + b) * HWSZ + h*WW + w] = j0 + lane;
    }
}

// ---------------- K4: sparse attention with Wo folded in, one direction ----------
__global__ void k_attn(const int* __restrict__ qcoor, int d)
{
    int lane = threadIdx.x & 31, wid = threadIdx.x >> 5;
    int grp = blockIdx.x * 8 + wid;
    if (grp >= GRPD) return;
    int b = grp / (NN/4);
    int j0 = (grp - b * (NN/4)) * 4;

    size_t base = (size_t)(d*BB + b) * NN + j0;
    size_t kvbase = (size_t)(d*BB + b) * NN;
    const int* lut = g_lut + (d*BB + b) * HWSZ;

    const int* qc = qcoor + (size_t)(b*NN + j0) * 2;
    int craw = (lane < 8) ? __ldg(&qc[lane]) : 0;

    int head = lane >> 4;
    float qv[4], siv[4];
    #pragma unroll
    for (int p = 0; p < 4; p++) qv[p] = g_q[(base+p)*32 + lane];
    #pragma unroll
    for (int p = 0; p < 4; p++) siv[p] = g_sinv[(base+p)*2 + head];

    float bo = g_bo[d][lane];
    float2 uin = *(const float2*)&g_uinv[d][lane][0];
    int sh_dh = (lane < 9) ? c_sh[lane][0] : 0;
    int sh_dw = (lane < 9) ? c_sh[lane][1] : 0;

    #pragma unroll
    for (int p = 0; p < 4; p++) {
        int h = __shfl_sync(~0u, craw, 2*p);
        int w = __shfl_sync(~0u, craw, 2*p + 1);

        int idx = -1;
        if (lane < 9) {
            int sh = h + sh_dh, sw = w + sh_dw;
            if ((unsigned)sh < (unsigned)HH && (unsigned)sw < (unsigned)WW)
                idx = __ldg(&lut[sh*WW + sw]);
        }
        unsigned vm = __ballot_sync(~0u, idx >= 0);
        float ninv = (float)(9 - __popc(vm));

        float si0 = __shfl_sync(~0u, siv[p], 0);
        float si1 = __shfl_sync(~0u, siv[p], 16);
        float m0 = si0, m1 = si1;
        float sum0 = ninv, sum1 = ninv;
        float acc0 = ninv * uin.x, acc1 = ninv * uin.y;

        unsigned mm = vm;
        while (mm) {
            int s = __ffs(mm) - 1; mm &= mm - 1;
            int id = __shfl_sync(~0u, idx, s);
            size_t off = kvbase + id;
            float kc = g_k[off*32 + lane];
            float pr = qv[p] * kc;
            pr += __shfl_xor_sync(~0u, pr, 8);
            pr += __shfl_xor_sync(~0u, pr, 4);
            pr += __shfl_xor_sync(~0u, pr, 2);
            pr += __shfl_xor_sync(~0u, pr, 1);
            pr *= 0.25f;
            float s0 = __shfl_sync(~0u, pr, 0);
            float s1 = __shfl_sync(~0u, pr, 16);
            float2 uu = g_u[off*32 + lane];
            float2 ee = *(const float2*)&g_pu[d][s][lane][0];

            float mn0 = fmaxf(m0, s0);
            float c0 = __expf(m0 - mn0), w0 = __expf(s0 - mn0);
            sum0 = sum0 * c0 + w0;
            acc0 = fmaf(acc0, c0, w0 * (uu.x + ee.x));
            m0 = mn0;

            float mn1 = fmaxf(m1, s1);
            float c1 = __expf(m1 - mn1), w1 = __expf(s1 - mn1);
            sum1 = sum1 * c1 + w1;
            acc1 = fmaf(acc1, c1, w1 * (uu.y + ee.y));
            m1 = mn1;
        }
        g_o[(base+p)*32 + lane] = bo + acc0 / sum0 + acc1 / sum1;
    }
}

// ---------------- K5: fused canvas zero + scatter, one direction -----------------
__global__ void k_scatter(float* __restrict__ out, int d)
{
    int pix = blockIdx.x * blockDim.x + threadIdx.x;
    if (pix >= HWSZ) return;
    int b = blockIdx.y;
    int db = d*BB + b;

    // query coords of direction d live in lut slot ((d^1)*BB + b)
    int idx = __ldg(&g_lut[((d ^ 1)*BB + b) * HWSZ + pix]);
    const float4* src = (const float4*)(g_o + ((size_t)db * NN + (idx < 0 ? 0 : idx)) * 32);
    float* dst = out + ((size_t)db * 32) * HWSZ + pix;

    #pragma unroll
    for (int c4 = 0; c4 < 8; c4++) {
        float4 v = make_float4(0.f, 0.f, 0.f, 0.f);
        if (idx >= 0) v = __ldg(&src[c4]);
        dst[(c4*4 + 0) * HWSZ] = v.x;
        dst[(c4*4 + 1) * HWSZ] = v.y;
        dst[(c4*4 + 2) * HWSZ] = v.z;
        dst[(c4*4 + 3) * HWSZ] = v.w;
    }
}

// --------------------------------- launch ---------------------------------------
extern "C" void kernel_launch(void* const* d_in, const int* in_sizes, int n_in,
                              void* d_out, int out_size)
{
    const float* li_f  = (const float*)d_in[0];
    const float* ra_f  = (const float*)d_in[1];
    const int*   li_c  = (const int*)d_in[2];
    const int*   ra_c  = (const int*)d_in[3];
    const float* li_nw = (const float*)d_in[4];
    const float* li_nb = (const float*)d_in[5];
    const float* ra_nw = (const float*)d_in[6];
    const float* ra_nb = (const float*)d_in[7];
    const float* qw1   = (const float*)d_in[8];
    const float* qb1   = (const float*)d_in[9];
    const float* qw2   = (const float*)d_in[10];
    const float* qb2   = (const float*)d_in[11];
    const float* posw  = (const float*)d_in[12];
    const float* posb  = (const float*)d_in[13];
    const float* iw1   = (const float*)d_in[14];
    const float* ib1   = (const float*)d_in[15];
    const float* ow1   = (const float*)d_in[16];
    const float* ob1   = (const float*)d_in[17];
    const float* iw2   = (const float*)d_in[18];
    const float* ib2   = (const float*)d_in[19];
    const float* ow2   = (const float*)d_in[20];
    const float* ob2   = (const float*)d_in[21];

    static cudaStream_t s_side = nullptr;
    static cudaEvent_t  ev_fork = nullptr, ev_sc0 = nullptr;
    if (!s_side) {
        cudaStreamCreateWithFlags(&s_side, cudaStreamNonBlocking);
        cudaEventCreateWithFlags(&ev_fork, cudaEventDisableTiming);
        cudaEventCreateWithFlags(&ev_sc0, cudaEventDisableTiming);
    }

    k_init<<<LUTB + 8, 1024>>>(qw1, qb1, qw2, qb2, posw, posb,
                               iw1, ib1, ow1, ob1, iw2, ib2, ow2, ob2);

    k_pre<<<(GRPS + 7)/8, 256>>>(li_f, ra_f, li_c, ra_c, li_nw, li_nb, ra_nw, ra_nb);

    // direction 0 attention, then its scatter forked to the side stream so it
    // overlaps direction-1 attention (scatter is DRAM-bound, attn issue-bound)
    k_attn<<<(GRPD + 7)/8, 256>>>(li_c, 0);
    cudaEventRecord(ev_fork, 0);
    cudaStreamWaitEvent(s_side, ev_fork, 0);
    k_scatter<<<dim3((HWSZ + 255)/256, BB), 256, 0, s_side>>>((float*)d_out, 0);
    cudaEventRecord(ev_sc0, s_side);

    k_attn<<<(GRPD + 7)/8, 256>>>(ra_c, 1);
    k_scatter<<<dim3((HWSZ + 255)/256, BB), 256>>>((float*)d_out, 1);

    // join side branch
    cudaStreamWaitEvent(0, ev_sc0, 0);
}

// round 13
// speedup vs baseline: 1.6917x; 1.0423x over previous
#include <cuda_runtime.h>
#include <cuda_bf16.h>
#include <cstdint>

#define BB 4
#define NN 20000
#define HH 448
#define WW 448
#define HWSZ (HH*WW)          // 200704
#define PTS (2*BB*NN)         // 160000 point-instances per role
#define GRPS (PTS/4)          // 40000 groups of 4 points
#define GRPD (GRPS/2)         // 20000 groups per direction
#define LUTB 196              // 2*BB*HWSZ ushorts / 8 per int4 / 1024 threads

// ---------------- device scratch (static globals; no runtime alloc) -------------
__device__ __align__(16) float  g_q[(size_t)PTS*32];
__device__ __align__(16) float  g_k[(size_t)PTS*32];
__device__ __align__(16) float2 g_u[(size_t)PTS*32];   // Wo-folded V, both heads
__device__ __align__(16) float  g_o[(size_t)PTS*32];   // final per-point output
__device__ float g_sinv[(size_t)PTS*2];
__device__ __align__(16) unsigned short g_lut[2*BB*HWSZ];   // 0xFFFF = empty

// weights, [in][out] so lane = out channel -> broadcast LDG
__device__ __align__(16) float g_Wq[2][32][32];
__device__ __align__(16) float g_Wk[2][32][32];
__device__ __align__(16) float g_Wu[2][32][32][2];     // folded Wo_h@Wv_eff_h
__device__ float g_bq[2][32], g_bkv[2][32], g_bkinv[2][32], g_bo[2][32];
__device__ __align__(8) float g_bu[2][32][2];          // Wo_h@bv0_h
__device__ __align__(8) float g_uinv[2][32][2];        // Wo_h@bvinv_h
__device__ __align__(8) float g_pu[2][9][32][2];       // Wo_h@pv_s_h

__constant__ int c_sh[9][2] = {{0,0},{-1,0},{1,0},{0,1},{-1,1},{1,1},{0,-1},{-1,-1},{1,-1}};

// ---------------- K1: LUT clear + fold weight chains (merged init) ---------------
__global__ void k_init(const float* qw1, const float* qb1,
                       const float* qw2, const float* qb2,
                       const float* posw, const float* posb,
                       const float* iw1, const float* ib1, const float* ow1, const float* ob1,
                       const float* iw2, const float* ib2, const float* ow2, const float* ob2)
{
    if (blockIdx.x < LUTB) {
        int i = blockIdx.x * 1024 + threadIdx.x;
        ((int4*)g_lut)[i] = make_int4(-1, -1, -1, -1);   // 8x 0xFFFF
        return;
    }
    int b2 = blockIdx.x - LUTB;   // 0..7
    int d = b2 >> 2;              // direction
    int m = b2 & 3;               // 0..3
    int t = threadIdx.x;
    const float* qkvw = d ? qw2 : qw1;
    const float* qkvb = d ? qb2 : qb1;
    const float* iw   = d ? iw2 : iw1;
    const float* ib   = d ? ib2 : ib1;
    const float* ow   = d ? ow2 : ow1;
    const float* ob   = d ? ob2 : ob1;

    int i = t >> 5, j = t & 31;   // i = out channel, j = in channel

    if (m == 0 || m == 1) {
        float acc = 0.f;
        #pragma unroll
        for (int c = 0; c < 32; c++)
            acc = fmaf(iw[(m*32+i)*32 + c], qkvw[(m*32+c)*32 + j], acc);
        if (m == 0) g_Wq[d][j][i] = acc;
        else        g_Wk[d][j][i] = acc;
    } else if (m == 2) {
        // Wv_eff then U_h = Wo_h @ Wv_eff_h
        __shared__ float s_wv[32][32];
        float acc = 0.f;
        #pragma unroll
        for (int c = 0; c < 32; c++)
            acc = fmaf(iw[(64+i)*32 + c], qkvw[(64+c)*32 + j], acc);
        s_wv[i][j] = acc;
        __syncthreads();
        float u0 = 0.f, u1 = 0.f;
        #pragma unroll
        for (int c = 0; c < 16; c++) {
            u0 = fmaf(ow[i*32 + c],      s_wv[c][j],      u0);
            u1 = fmaf(ow[i*32 + 16 + c], s_wv[16 + c][j], u1);
        }
        g_Wu[d][j][i][0] = u0;
        g_Wu[d][j][i][1] = u1;
    } else {
        // biases, pos-folds, and their Wo-folds
        __shared__ float s_bv0[32];
        __shared__ float s_pv[9][32];
        if (t < 32) {
            int i2 = t;
            float aq = ib[i2], ak = ib[32+i2], av = ib[64+i2];
            #pragma unroll
            for (int c = 0; c < 32; c++) {
                aq = fmaf(iw[i2*32 + c],        qkvb[c],      aq);
                ak = fmaf(iw[(32+i2)*32 + c],   qkvb[32+c],   ak);
                av = fmaf(iw[(64+i2)*32 + c],   qkvb[64+c],   av);
            }
            g_bq[d][i2]    = aq;
            g_bkv[d][i2]   = ak;
            g_bkinv[d][i2] = ib[32+i2];
            g_bo[d][i2]    = ob[i2];
            s_bv0[i2]      = av;
        } else if (t < 32 + 9*32) {
            int s = (t - 32) >> 5, i2 = t & 31;
            float acc = 0.f;
            #pragma unroll
            for (int c = 0; c < 32; c++) {
                float pc = (float)c_sh[s][0]*posw[2*c] + (float)c_sh[s][1]*posw[2*c+1] + posb[c];
                acc = fmaf(iw[(64+i2)*32 + c], pc, acc);
            }
            s_pv[s][i2] = acc;
        }
        __syncthreads();
        if (t < 64) {
            int h = t >> 5, i2 = t & 31;
            float a = 0.f;
            #pragma unroll
            for (int c = 0; c < 16; c++)
                a = fmaf(ow[i2*32 + h*16 + c], s_bv0[h*16 + c], a);
            g_bu[d][i2][h] = a;
        } else if (t < 128) {
            int tt = t - 64, h = tt >> 5, i2 = tt & 31;
            float a = 0.f;
            #pragma unroll
            for (int c = 0; c < 16; c++)
                a = fmaf(ow[i2*32 + h*16 + c], ib[64 + h*16 + c], a);
            g_uinv[d][i2][h] = a;
        } else if (t < 128 + 9*64) {
            int tt = t - 128;
            int s = tt / 64, r = tt & 63, h = r >> 5, i2 = r & 31;
            float a = 0.f;
            #pragma unroll
            for (int c = 0; c < 16; c++)
                a = fmaf(ow[i2*32 + h*16 + c], s_pv[s][h*16 + c], a);
            g_pu[d][s][i2][h] = a;
        }
    }
}

// ---------------- K3: layernorm + q/k/u projections, 4 points per warp -----------
__global__ void k_pre(const float* __restrict__ li_f, const float* __restrict__ ra_f,
                      const int* __restrict__ li_c, const int* __restrict__ ra_c,
                      const float* __restrict__ li_nw, const float* __restrict__ li_nb,
                      const float* __restrict__ ra_nw, const float* __restrict__ ra_nb)
{
    __shared__ float4 sb4[8][32];       // [wid][chan] -> 4 points per float4
    int lane = threadIdx.x & 31, wid = threadIdx.x >> 5;
    int grp = blockIdx.x * 8 + wid;
    if (grp >= GRPS) return;
    int set = grp / GRPD;                     // 0..1
    int rem = grp - set * GRPD;               // 0..19999
    int b = rem / (NN/4);
    int j0 = (rem - b * (NN/4)) * 4;

    const float* feat = (set ? ra_f : li_f) + (size_t)(b*NN + j0) * 32;
    float nw = (set ? ra_nw : li_nw)[lane];
    float nbv = (set ? ra_nb : li_nb)[lane];

    // front-batched loads (MLP=4)
    float x[4];
    #pragma unroll
    for (int p = 0; p < 4; p++) x[p] = feat[p*32 + lane];

    float* sbf = (float*)&sb4[wid][lane];
    #pragma unroll
    for (int p = 0; p < 4; p++) {
        float s = x[p];
        #pragma unroll
        for (int o = 16; o; o >>= 1) s += __shfl_xor_sync(~0u, s, o);
        float mu = s * (1.f/32.f);
        float dx = x[p] - mu;
        float vv = dx * dx;
        #pragma unroll
        for (int o = 16; o; o >>= 1) vv += __shfl_xor_sync(~0u, vv, o);
        sbf[p] = dx * rsqrtf(vv * (1.f/32.f) + 1e-5f) * nw + nbv;
    }
    __syncwarp();

    int dq = set, dk = set ^ 1;
    float aq[4], ak[4], au0[4], au1[4];
    float bqv = g_bq[dq][lane], bkv = g_bkv[dk][lane];
    float bu0 = g_bu[dk][lane][0], bu1 = g_bu[dk][lane][1];
    #pragma unroll
    for (int p = 0; p < 4; p++) { aq[p]=bqv; ak[p]=bkv; au0[p]=bu0; au1[p]=bu1; }

    #pragma unroll 4
    for (int c = 0; c < 32; c++) {
        float wq = g_Wq[dq][c][lane];
        float wk = g_Wk[dk][c][lane];
        float2 wu = *(const float2*)&g_Wu[dk][c][lane][0];
        float4 f = sb4[wid][c];         // one LDS.128, broadcast
        aq[0]  = fmaf(f.x, wq, aq[0]);   aq[1]  = fmaf(f.y, wq, aq[1]);
        aq[2]  = fmaf(f.z, wq, aq[2]);   aq[3]  = fmaf(f.w, wq, aq[3]);
        ak[0]  = fmaf(f.x, wk, ak[0]);   ak[1]  = fmaf(f.y, wk, ak[1]);
        ak[2]  = fmaf(f.z, wk, ak[2]);   ak[3]  = fmaf(f.w, wk, ak[3]);
        au0[0] = fmaf(f.x, wu.x, au0[0]); au0[1] = fmaf(f.y, wu.x, au0[1]);
        au0[2] = fmaf(f.z, wu.x, au0[2]); au0[3] = fmaf(f.w, wu.x, au0[3]);
        au1[0] = fmaf(f.x, wu.y, au1[0]); au1[1] = fmaf(f.y, wu.y, au1[1]);
        au1[2] = fmaf(f.z, wu.y, au1[2]); au1[3] = fmaf(f.w, wu.y, au1[3]);
    }

    size_t pq = ((size_t)(dq*BB + b) * NN + j0);
    size_t pk = ((size_t)(dk*BB + b) * NN + j0);
    float bki = g_bkinv[dq][lane];
    #pragma unroll
    for (int p = 0; p < 4; p++) {
        g_q[(pq+p)*32 + lane] = aq[p];
        g_k[(pk+p)*32 + lane] = ak[p];
        g_u[(pk+p)*32 + lane] = make_float2(au0[p], au1[p]);
        // invalid-neighbor score: dot(q, bk_inv)/4 per head
        float pr = aq[p] * bki;
        pr += __shfl_xor_sync(~0u, pr, 8);
        pr += __shfl_xor_sync(~0u, pr, 4);
        pr += __shfl_xor_sync(~0u, pr, 2);
        pr += __shfl_xor_sync(~0u, pr, 1);
        if ((lane & 15) == 0) g_sinv[(pq+p)*2 + (lane >> 4)] = pr * 0.25f;
    }

    if (lane < 4) {
        const int* cc = (set ? ra_c : li_c) + (size_t)(b*NN + j0 + lane) * 2;
        int h = __ldg(&cc[0]), w = __ldg(&cc[1]);
        g_lut[(dk*BB + b) * HWSZ + h*WW + w] = (unsigned short)(j0 + lane);
    }
}

// ---------------- K4: sparse attention with Wo folded in, both directions --------
__global__ void k_attn(const int* __restrict__ li_c, const int* __restrict__ ra_c)
{
    int lane = threadIdx.x & 31, wid = threadIdx.x >> 5;
    int grp = blockIdx.x * 8 + wid;
    if (grp >= GRPS) return;
    int d = grp / GRPD;
    int rem = grp - d * GRPD;
    int b = rem / (NN/4);
    int j0 = (rem - b * (NN/4)) * 4;

    size_t base = (size_t)(d*BB + b) * NN + j0;
    size_t kvbase = (size_t)(d*BB + b) * NN;
    const unsigned short* lut = g_lut + (d*BB + b) * HWSZ;

    const int* qc = (d == 0 ? li_c : ra_c) + (size_t)(b*NN + j0) * 2;
    int craw = (lane < 8) ? __ldg(&qc[lane]) : 0;

    int head = lane >> 4;
    float qv[4], siv[4];
    #pragma unroll
    for (int p = 0; p < 4; p++) qv[p] = g_q[(base+p)*32 + lane];
    #pragma unroll
    for (int p = 0; p < 4; p++) siv[p] = g_sinv[(base+p)*2 + head];

    float bo = g_bo[d][lane];
    float2 uin = *(const float2*)&g_uinv[d][lane][0];
    int sh_dh = (lane < 9) ? c_sh[lane][0] : 0;
    int sh_dw = (lane < 9) ? c_sh[lane][1] : 0;

    #pragma unroll
    for (int p = 0; p < 4; p++) {
        int h = __shfl_sync(~0u, craw, 2*p);
        int w = __shfl_sync(~0u, craw, 2*p + 1);

        int idx = -1;
        if (lane < 9) {
            int sh = h + sh_dh, sw = w + sh_dw;
            if ((unsigned)sh < (unsigned)HH && (unsigned)sw < (unsigned)WW) {
                unsigned v = __ldg(&lut[sh*WW + sw]);
                idx = (v == 0xFFFFu) ? -1 : (int)v;
            }
        }
        unsigned vm = __ballot_sync(~0u, idx >= 0);
        float ninv = (float)(9 - __popc(vm));

        float si0 = __shfl_sync(~0u, siv[p], 0);
        float si1 = __shfl_sync(~0u, siv[p], 16);
        float m0 = si0, m1 = si1;
        float sum0 = ninv, sum1 = ninv;
        float acc0 = ninv * uin.x, acc1 = ninv * uin.y;

        unsigned mm = vm;
        while (mm) {
            int s = __ffs(mm) - 1; mm &= mm - 1;
            int id = __shfl_sync(~0u, idx, s);
            size_t off = kvbase + id;
            float kc = g_k[off*32 + lane];
            float pr = qv[p] * kc;
            pr += __shfl_xor_sync(~0u, pr, 8);
            pr += __shfl_xor_sync(~0u, pr, 4);
            pr += __shfl_xor_sync(~0u, pr, 2);
            pr += __shfl_xor_sync(~0u, pr, 1);
            pr *= 0.25f;
            float s0 = __shfl_sync(~0u, pr, 0);
            float s1 = __shfl_sync(~0u, pr, 16);
            float2 uu = g_u[off*32 + lane];
            float2 ee = *(const float2*)&g_pu[d][s][lane][0];

            float mn0 = fmaxf(m0, s0);
            float c0 = __expf(m0 - mn0), w0 = __expf(s0 - mn0);
            sum0 = sum0 * c0 + w0;
            acc0 = fmaf(acc0, c0, w0 * (uu.x + ee.x));
            m0 = mn0;

            float mn1 = fmaxf(m1, s1);
            float c1 = __expf(m1 - mn1), w1 = __expf(s1 - mn1);
            sum1 = sum1 * c1 + w1;
            acc1 = fmaf(acc1, c1, w1 * (uu.y + ee.y));
            m1 = mn1;
        }
        g_o[(base+p)*32 + lane] = bo + acc0 / sum0 + acc1 / sum1;
    }
}

// ---------------- K5: fused canvas zero + scatter (canvas-major, coalesced) ------
__global__ void k_scatter(float* __restrict__ out)
{
    int pix = blockIdx.x * blockDim.x + threadIdx.x;
    if (pix >= HWSZ) return;
    int db = blockIdx.y;
    int d = db >> 2, b = db & 3;

    // query coords of direction d live in lut slot ((d^1)*BB + b)
    unsigned v = __ldg(&g_lut[((d ^ 1)*BB + b) * HWSZ + pix]);
    int idx = (v == 0xFFFFu) ? -1 : (int)v;
    const float4* src = (const float4*)(g_o + ((size_t)db * NN + (idx < 0 ? 0 : idx)) * 32);
    float* dst = out + ((size_t)db * 32) * HWSZ + pix;

    #pragma unroll
    for (int c4 = 0; c4 < 8; c4++) {
        float4 vv = make_float4(0.f, 0.f, 0.f, 0.f);
        if (idx >= 0) vv = __ldg(&src[c4]);
        dst[(c4*4 + 0) * HWSZ] = vv.x;
        dst[(c4*4 + 1) * HWSZ] = vv.y;
        dst[(c4*4 + 2) * HWSZ] = vv.z;
        dst[(c4*4 + 3) * HWSZ] = vv.w;
    }
}

// --------------------------------- launch ---------------------------------------
extern "C" void kernel_launch(void* const* d_in, const int* in_sizes, int n_in,
                              void* d_out, int out_size)
{
    const float* li_f  = (const float*)d_in[0];
    const float* ra_f  = (const float*)d_in[1];
    const int*   li_c  = (const int*)d_in[2];
    const int*   ra_c  = (const int*)d_in[3];
    const float* li_nw = (const float*)d_in[4];
    const float* li_nb = (const float*)d_in[5];
    const float* ra_nw = (const float*)d_in[6];
    const float* ra_nb = (const float*)d_in[7];
    const float* qw1   = (const float*)d_in[8];
    const float* qb1   = (const float*)d_in[9];
    const float* qw2   = (const float*)d_in[10];
    const float* qb2   = (const float*)d_in[11];
    const float* posw  = (const float*)d_in[12];
    const float* posb  = (const float*)d_in[13];
    const float* iw1   = (const float*)d_in[14];
    const float* ib1   = (const float*)d_in[15];
    const float* ow1   = (const float*)d_in[16];
    const float* ob1   = (const float*)d_in[17];
    const float* iw2   = (const float*)d_in[18];
    const float* ib2   = (const float*)d_in[19];
    const float* ow2   = (const float*)d_in[20];
    const float* ob2   = (const float*)d_in[21];

    k_init<<<LUTB + 8, 1024>>>(qw1, qb1, qw2, qb2, posw, posb,
                               iw1, ib1, ow1, ob1, iw2, ib2, ow2, ob2);

    k_pre<<<(GRPS + 7)/8, 256>>>(li_f, ra_f, li_c, ra_c, li_nw, li_nb, ra_nw, ra_nb);

    k_attn<<<(GRPS + 7)/8, 256>>>(li_c, ra_c);

    k_scatter<<<dim3((HWSZ + 255)/256, 2*BB), 256>>>((float*)d_out);
}

// round 14
// speedup vs baseline: 1.7473x; 1.0329x over previous
#include <cuda_runtime.h>
#include <cuda_bf16.h>
#include <cstdint>

#define BB 4
#define NN 20000
#define HH 448
#define WW 448
#define HWSZ (HH*WW)          // 200704
#define PTS (2*BB*NN)         // 160000 point-instances per role
#define GRPS (PTS/4)          // 40000 groups of 4 points
#define GRPD (GRPS/2)         // 20000 groups per direction
#define LUTB 196              // 2*BB*HWSZ ushorts / 8 per int4 / 1024 threads

// ---------------- device scratch (static globals; no runtime alloc) -------------
__device__ __align__(16) float g_q[(size_t)PTS*32];
__device__ __align__(16) float g_k[(size_t)PTS*32];
__device__ __align__(16) float g_v[(size_t)PTS*32];
__device__ __align__(16) float g_o[(size_t)PTS*32];   // compact attention output
__device__ float g_sinv[(size_t)PTS*2];
__device__ __align__(16) unsigned short g_lut[2*BB*HWSZ];   // 0xFFFF = empty

// [dir][m][in_ch][out_ch]; m: 0=q 1=k 2=v 3=out  (lane = out channel -> broadcast)
__device__ __align__(16) float g_W[2][4][32][32];
__device__ float g_bq[2][32], g_bkv[2][32], g_bkinv[2][32];
__device__ float g_bv0[2][32], g_bvinv[2][32], g_bo[2][32];
__device__ __align__(16) float g_pv[2][9][32];

__constant__ int c_sh[9][2] = {{0,0},{-1,0},{1,0},{0,1},{-1,1},{1,1},{0,-1},{-1,-1},{1,-1}};

// ---------------- K1: LUT clear + fold weight chains (merged init) ---------------
__global__ void k_init(const float* qw1, const float* qb1,
                       const float* qw2, const float* qb2,
                       const float* posw, const float* posb,
                       const float* iw1, const float* ib1, const float* ow1, const float* ob1,
                       const float* iw2, const float* ib2, const float* ow2, const float* ob2)
{
    if (blockIdx.x < LUTB) {
        int i = blockIdx.x * 1024 + threadIdx.x;
        ((int4*)g_lut)[i] = make_int4(-1, -1, -1, -1);   // 8x 0xFFFF
        return;
    }
    int b2 = blockIdx.x - LUTB;   // 0..7
    int d = b2 >> 2;              // direction
    int m = b2 & 3;               // 0..3
    int t = threadIdx.x;
    const float* qkvw = d ? qw2 : qw1;
    const float* qkvb = d ? qb2 : qb1;
    const float* iw   = d ? iw2 : iw1;
    const float* ib   = d ? ib2 : ib1;
    const float* ow   = d ? ow2 : ow1;
    const float* ob   = d ? ob2 : ob1;

    int i = t >> 5, j = t & 31;   // i = out channel, j = in channel
    if (m < 3) {
        // Weff[i][j] = sum_c in_w[m*32+i][c] * qkv_w[m][c][j]; store [in][out]
        float acc = 0.f;
        #pragma unroll
        for (int c = 0; c < 32; c++)
            acc = fmaf(iw[(m*32+i)*32 + c], qkvw[(m*32+c)*32 + j], acc);
        g_W[d][m][j][i] = acc;
    } else {
        g_W[d][3][j][i] = ow[i*32 + j];   // store [in][out]
        if (t < 32) {
            int i2 = t;
            float aq = ib[i2], ak = ib[32+i2], av = ib[64+i2];
            #pragma unroll
            for (int c = 0; c < 32; c++) {
                aq = fmaf(iw[i2*32 + c],        qkvb[c],      aq);
                ak = fmaf(iw[(32+i2)*32 + c],   qkvb[32+c],   ak);
                av = fmaf(iw[(64+i2)*32 + c],   qkvb[64+c],   av);
            }
            g_bq[d][i2]    = aq;
            g_bkv[d][i2]   = ak;
            g_bkinv[d][i2] = ib[32+i2];
            g_bv0[d][i2]   = av;
            g_bvinv[d][i2] = ib[64+i2];
            g_bo[d][i2]    = ob[i2];
        } else if (t < 32 + 9*32) {
            int s = (t - 32) >> 5, i2 = t & 31;
            float acc = 0.f;
            #pragma unroll
            for (int c = 0; c < 32; c++) {
                float pc = (float)c_sh[s][0]*posw[2*c] + (float)c_sh[s][1]*posw[2*c+1] + posb[c];
                acc = fmaf(iw[(64+i2)*32 + c], pc, acc);
            }
            g_pv[d][s][i2] = acc;
        }
    }
}

// ---------------- K3: layernorm + projections, 4 points per warp -----------------
__global__ void k_pre(const float* __restrict__ li_f, const float* __restrict__ ra_f,
                      const int* __restrict__ li_c, const int* __restrict__ ra_c,
                      const float* __restrict__ li_nw, const float* __restrict__ li_nb,
                      const float* __restrict__ ra_nw, const float* __restrict__ ra_nb)
{
    __shared__ float4 sb4[8][32];       // [wid][chan] -> 4 points per float4
    int lane = threadIdx.x & 31, wid = threadIdx.x >> 5;
    int grp = blockIdx.x * 8 + wid;
    if (grp >= GRPS) return;
    int set = grp / GRPD;                     // 0..1
    int rem = grp - set * GRPD;               // 0..19999
    int b = rem / (NN/4);
    int j0 = (rem - b * (NN/4)) * 4;

    const float* feat = (set ? ra_f : li_f) + (size_t)(b*NN + j0) * 32;
    float nw = (set ? ra_nw : li_nw)[lane];
    float nbv = (set ? ra_nb : li_nb)[lane];

    // front-batched loads (MLP=4)
    float x[4];
    #pragma unroll
    for (int p = 0; p < 4; p++) x[p] = feat[p*32 + lane];

    float* sbf = (float*)&sb4[wid][lane];
    #pragma unroll
    for (int p = 0; p < 4; p++) {
        float s = x[p];
        #pragma unroll
        for (int o = 16; o; o >>= 1) s += __shfl_xor_sync(~0u, s, o);
        float mu = s * (1.f/32.f);
        float dx = x[p] - mu;
        float vv = dx * dx;
        #pragma unroll
        for (int o = 16; o; o >>= 1) vv += __shfl_xor_sync(~0u, vv, o);
        sbf[p] = dx * rsqrtf(vv * (1.f/32.f) + 1e-5f) * nw + nbv;
    }
    __syncwarp();

    int dq = set, dk = set ^ 1;
    float aq[4], ak[4], av[4];
    float bqv = g_bq[dq][lane], bkv = g_bkv[dk][lane], bvv = g_bv0[dk][lane];
    #pragma unroll
    for (int p = 0; p < 4; p++) { aq[p] = bqv; ak[p] = bkv; av[p] = bvv; }

    #pragma unroll 4
    for (int c = 0; c < 32; c++) {
        float wq = g_W[dq][0][c][lane];
        float wk = g_W[dk][1][c][lane];
        float wv = g_W[dk][2][c][lane];
        float4 f = sb4[wid][c];         // one LDS.128, broadcast
        aq[0] = fmaf(f.x, wq, aq[0]); aq[1] = fmaf(f.y, wq, aq[1]);
        aq[2] = fmaf(f.z, wq, aq[2]); aq[3] = fmaf(f.w, wq, aq[3]);
        ak[0] = fmaf(f.x, wk, ak[0]); ak[1] = fmaf(f.y, wk, ak[1]);
        ak[2] = fmaf(f.z, wk, ak[2]); ak[3] = fmaf(f.w, wk, ak[3]);
        av[0] = fmaf(f.x, wv, av[0]); av[1] = fmaf(f.y, wv, av[1]);
        av[2] = fmaf(f.z, wv, av[2]); av[3] = fmaf(f.w, wv, av[3]);
    }

    size_t pq = ((size_t)(dq*BB + b) * NN + j0);
    size_t pk = ((size_t)(dk*BB + b) * NN + j0);
    float bki = g_bkinv[dq][lane];
    #pragma unroll
    for (int p = 0; p < 4; p++) {
        g_q[(pq+p)*32 + lane] = aq[p];
        g_k[(pk+p)*32 + lane] = ak[p];
        g_v[(pk+p)*32 + lane] = av[p];
        // invalid-neighbor score: dot(q, bk_inv)/4 per head
        float pr = aq[p] * bki;
        pr += __shfl_xor_sync(~0u, pr, 8);
        pr += __shfl_xor_sync(~0u, pr, 4);
        pr += __shfl_xor_sync(~0u, pr, 2);
        pr += __shfl_xor_sync(~0u, pr, 1);
        if ((lane & 15) == 0) g_sinv[(pq+p)*2 + (lane >> 4)] = pr * 0.25f;
    }

    if (lane < 4) {
        const int* cc = (set ? ra_c : li_c) + (size_t)(b*NN + j0 + lane) * 2;
        int h = __ldg(&cc[0]), w = __ldg(&cc[1]);
        g_lut[(dk*BB + b) * HWSZ + h*WW + w] = (unsigned short)(j0 + lane);
    }
}

// ---------------- K4: sparse attention, 4 points per warp, one direction ---------
__global__ void k_attn(const int* __restrict__ qcoor, int d)
{
    __shared__ float4 sb4[8][32];
    int lane = threadIdx.x & 31, wid = threadIdx.x >> 5;
    int grp = blockIdx.x * 8 + wid;
    if (grp >= GRPD) return;
    int b = grp / (NN/4);
    int j0 = (grp - b * (NN/4)) * 4;

    size_t base = (size_t)(d*BB + b) * NN + j0;     // q / o / sinv rows
    size_t kvbase = (size_t)(d*BB + b) * NN;        // kv pool (other modality)
    const unsigned short* lut = g_lut + (d*BB + b) * HWSZ;

    const int* qc = qcoor + (size_t)(b*NN + j0) * 2;
    int craw = (lane < 8) ? __ldg(&qc[lane]) : 0;

    int head = lane >> 4;

    // front-batched independent loads (MLP=8)
    float qv[4], siv[4];
    #pragma unroll
    for (int p = 0; p < 4; p++) qv[p] = g_q[(base+p)*32 + lane];
    #pragma unroll
    for (int p = 0; p < 4; p++) siv[p] = g_sinv[(base+p)*2 + head];

    float bvi = g_bvinv[d][lane];
    int sh_dh = (lane < 9) ? c_sh[lane][0] : 0;
    int sh_dw = (lane < 9) ? c_sh[lane][1] : 0;

    float* sbf = (float*)&sb4[wid][lane];
    #pragma unroll
    for (int p = 0; p < 4; p++) {
        int h = __shfl_sync(~0u, craw, 2*p);
        int w = __shfl_sync(~0u, craw, 2*p + 1);

        // lane-parallel probe: lane s<9 checks shift s
        int idx = -1;
        if (lane < 9) {
            int sh = h + sh_dh, sw = w + sh_dw;
            if ((unsigned)sh < (unsigned)HH && (unsigned)sw < (unsigned)WW) {
                unsigned v = __ldg(&lut[sh*WW + sw]);
                idx = (v == 0xFFFFu) ? -1 : (int)v;
            }
        }
        unsigned vm = __ballot_sync(~0u, idx >= 0);
        int nval = __popc(vm);

        // online softmax seeded with invalid class (9-nval copies of score sinv)
        float m_run = siv[p];
        float ssum = (float)(9 - nval);
        float o = ssum * bvi;

        unsigned mm = vm;
        while (mm) {
            int s = __ffs(mm) - 1; mm &= mm - 1;
            int id = __shfl_sync(~0u, idx, s);
            size_t off = (kvbase + id) * 32 + lane;
            float kc = g_k[off];
            float pr = qv[p] * kc;
            pr += __shfl_xor_sync(~0u, pr, 8);
            pr += __shfl_xor_sync(~0u, pr, 4);
            pr += __shfl_xor_sync(~0u, pr, 2);
            pr += __shfl_xor_sync(~0u, pr, 1);
            pr *= 0.25f;
            float vval = g_v[off] + g_pv[d][s][lane];
            float mnew = fmaxf(m_run, pr);
            float corr = __expf(m_run - mnew);
            float wgt  = __expf(pr - mnew);
            ssum = ssum * corr + wgt;
            o = fmaf(o, corr, wgt * vval);
            m_run = mnew;
        }
        sbf[p] = o / ssum;
    }
    __syncwarp();

    // out-projection, weights + LDS.128 reused across 4 points
    float acc[4];
    float bo = g_bo[d][lane];
    #pragma unroll
    for (int p = 0; p < 4; p++) acc[p] = bo;
    #pragma unroll 4
    for (int c = 0; c < 32; c++) {
        float wo = g_W[d][3][c][lane];
        float4 f = sb4[wid][c];         // one LDS.128, broadcast
        acc[0] = fmaf(f.x, wo, acc[0]);
        acc[1] = fmaf(f.y, wo, acc[1]);
        acc[2] = fmaf(f.z, wo, acc[2]);
        acc[3] = fmaf(f.w, wo, acc[3]);
    }
    #pragma unroll
    for (int p = 0; p < 4; p++)
        g_o[(base+p)*32 + lane] = acc[p];
}

// ---------------- K5: fused canvas zero + scatter, one direction -----------------
__global__ void k_scatter(float* __restrict__ out, int d)
{
    int pix = blockIdx.x * blockDim.x + threadIdx.x;
    if (pix >= HWSZ) return;
    int b = blockIdx.y;
    int db = d*BB + b;

    // query coords of direction d live in lut slot ((d^1)*BB + b)
    unsigned v = __ldg(&g_lut[((d ^ 1)*BB + b) * HWSZ + pix]);
    int idx = (v == 0xFFFFu) ? -1 : (int)v;
    const float4* src = (const float4*)(g_o + ((size_t)db * NN + (idx < 0 ? 0 : idx)) * 32);
    float* dst = out + ((size_t)db * 32) * HWSZ + pix;

    #pragma unroll
    for (int c4 = 0; c4 < 8; c4++) {
        float4 vv = make_float4(0.f, 0.f, 0.f, 0.f);
        if (idx >= 0) vv = __ldg(&src[c4]);
        dst[(c4*4 + 0) * HWSZ] = vv.x;
        dst[(c4*4 + 1) * HWSZ] = vv.y;
        dst[(c4*4 + 2) * HWSZ] = vv.z;
        dst[(c4*4 + 3) * HWSZ] = vv.w;
    }
}

// --------------------------------- launch ---------------------------------------
extern "C" void kernel_launch(void* const* d_in, const int* in_sizes, int n_in,
                              void* d_out, int out_size)
{
    const float* li_f  = (const float*)d_in[0];
    const float* ra_f  = (const float*)d_in[1];
    const int*   li_c  = (const int*)d_in[2];
    const int*   ra_c  = (const int*)d_in[3];
    const float* li_nw = (const float*)d_in[4];
    const float* li_nb = (const float*)d_in[5];
    const float* ra_nw = (const float*)d_in[6];
    const float* ra_nb = (const float*)d_in[7];
    const float* qw1   = (const float*)d_in[8];
    const float* qb1   = (const float*)d_in[9];
    const float* qw2   = (const float*)d_in[10];
    const float* qb2   = (const float*)d_in[11];
    const float* posw  = (const float*)d_in[12];
    const float* posb  = (const float*)d_in[13];
    const float* iw1   = (const float*)d_in[14];
    const float* ib1   = (const float*)d_in[15];
    const float* ow1   = (const float*)d_in[16];
    const float* ob1   = (const float*)d_in[17];
    const float* iw2   = (const float*)d_in[18];
    const float* ib2   = (const float*)d_in[19];
    const float* ow2   = (const float*)d_in[20];
    const float* ob2   = (const float*)d_in[21];

    static cudaStream_t s_side = nullptr;
    static cudaEvent_t  ev_fork = nullptr, ev_sc0 = nullptr;
    if (!s_side) {
        cudaStreamCreateWithFlags(&s_side, cudaStreamNonBlocking);
        cudaEventCreateWithFlags(&ev_fork, cudaEventDisableTiming);
        cudaEventCreateWithFlags(&ev_sc0, cudaEventDisableTiming);
    }

    k_init<<<LUTB + 8, 1024>>>(qw1, qb1, qw2, qb2, posw, posb,
                               iw1, ib1, ow1, ob1, iw2, ib2, ow2, ob2);

    k_pre<<<(GRPS + 7)/8, 256>>>(li_f, ra_f, li_c, ra_c, li_nw, li_nb, ra_nw, ra_nb);

    // direction 0: attention, then scatter forked onto side stream so the
    // DRAM-bound scatter overlaps the issue-bound direction-1 attention
    k_attn<<<(GRPD + 7)/8, 256>>>(li_c, 0);
    cudaEventRecord(ev_fork, 0);
    cudaStreamWaitEvent(s_side, ev_fork, 0);
    k_scatter<<<dim3((HWSZ + 255)/256, BB), 256, 0, s_side>>>((float*)d_out, 0);
    cudaEventRecord(ev_sc0, s_side);

    // direction 1 on the main stream
    k_attn<<<(GRPD + 7)/8, 256>>>(ra_c, 1);
    k_scatter<<<dim3((HWSZ + 255)/256, BB), 256>>>((float*)d_out, 1);

    // join side branch
    cudaStreamWaitEvent(0, ev_sc0, 0);
}

// round 15
// speedup vs baseline: 1.9403x; 1.1105x over previous
#include <cuda_runtime.h>
#include <cuda_bf16.h>
#include <cstdint>

#define BB 4
#define NN 20000
#define HH 448
#define WW 448
#define HWSZ (HH*WW)          // 200704
#define PTS (2*BB*NN)         // 160000 point-instances per role
#define GRPS (PTS/4)          // 40000 groups of 4 points (k_attn)
#define GRPD (GRPS/2)
#define GRP8 (PTS/8)          // 20000 groups of 8 points (k_pre)
#define GRP8D (GRP8/2)
#define LUTB 196              // 2*BB*HWSZ ushorts / 8 per int4 / 1024 threads

// ---------------- device scratch (static globals; no runtime alloc) -------------
__device__ __align__(16) float g_q[(size_t)PTS*32];
__device__ __align__(16) float g_k[(size_t)PTS*32];
__device__ __align__(16) float g_v[(size_t)PTS*32];
__device__ __align__(16) float g_o[(size_t)PTS*32];   // compact attention output
__device__ float g_sinv[(size_t)PTS*2];
__device__ __align__(16) unsigned short g_lut[2*BB*HWSZ];   // 0xFFFF = empty

// [dir][m][in_ch][out_ch]; m: 0=q 1=k 2=v 3=out  (lane = out channel -> broadcast)
__device__ __align__(16) float g_W[2][4][32][32];
__device__ float g_bq[2][32], g_bkv[2][32], g_bkinv[2][32];
__device__ float g_bv0[2][32], g_bvinv[2][32], g_bo[2][32];
__device__ __align__(16) float g_pv[2][9][32];

__constant__ int c_sh[9][2] = {{0,0},{-1,0},{1,0},{0,1},{-1,1},{1,1},{0,-1},{-1,-1},{1,-1}};

// ---------------- K1: LUT clear + fold weight chains (merged init) ---------------
__global__ void k_init(const float* qw1, const float* qb1,
                       const float* qw2, const float* qb2,
                       const float* posw, const float* posb,
                       const float* iw1, const float* ib1, const float* ow1, const float* ob1,
                       const float* iw2, const float* ib2, const float* ow2, const float* ob2)
{
    if (blockIdx.x < LUTB) {
        int i = blockIdx.x * 1024 + threadIdx.x;
        ((int4*)g_lut)[i] = make_int4(-1, -1, -1, -1);   // 8x 0xFFFF
        return;
    }
    int b2 = blockIdx.x - LUTB;   // 0..7
    int d = b2 >> 2;              // direction
    int m = b2 & 3;               // 0..3
    int t = threadIdx.x;
    const float* qkvw = d ? qw2 : qw1;
    const float* qkvb = d ? qb2 : qb1;
    const float* iw   = d ? iw2 : iw1;
    const float* ib   = d ? ib2 : ib1;
    const float* ow   = d ? ow2 : ow1;
    const float* ob   = d ? ob2 : ob1;

    int i = t >> 5, j = t & 31;   // i = out channel, j = in channel
    if (m < 3) {
        // Weff[i][j] = sum_c in_w[m*32+i][c] * qkv_w[m][c][j]; store [in][out]
        float acc = 0.f;
        #pragma unroll
        for (int c = 0; c < 32; c++)
            acc = fmaf(iw[(m*32+i)*32 + c], qkvw[(m*32+c)*32 + j], acc);
        g_W[d][m][j][i] = acc;
    } else {
        g_W[d][3][j][i] = ow[i*32 + j];   // store [in][out]
        if (t < 32) {
            int i2 = t;
            float aq = ib[i2], ak = ib[32+i2], av = ib[64+i2];
            #pragma unroll
            for (int c = 0; c < 32; c++) {
                aq = fmaf(iw[i2*32 + c],        qkvb[c],      aq);
                ak = fmaf(iw[(32+i2)*32 + c],   qkvb[32+c],   ak);
                av = fmaf(iw[(64+i2)*32 + c],   qkvb[64+c],   av);
            }
            g_bq[d][i2]    = aq;
            g_bkv[d][i2]   = ak;
            g_bkinv[d][i2] = ib[32+i2];
            g_bv0[d][i2]   = av;
            g_bvinv[d][i2] = ib[64+i2];
            g_bo[d][i2]    = ob[i2];
        } else if (t < 32 + 9*32) {
            int s = (t - 32) >> 5, i2 = t & 31;
            float acc = 0.f;
            #pragma unroll
            for (int c = 0; c < 32; c++) {
                float pc = (float)c_sh[s][0]*posw[2*c] + (float)c_sh[s][1]*posw[2*c+1] + posb[c];
                acc = fmaf(iw[(64+i2)*32 + c], pc, acc);
            }
            g_pv[d][s][i2] = acc;
        }
    }
}

// ---------------- K3: layernorm + projections, 8 points per warp -----------------
__global__ void k_pre(const float* __restrict__ li_f, const float* __restrict__ ra_f,
                      const int* __restrict__ li_c, const int* __restrict__ ra_c,
                      const float* __restrict__ li_nw, const float* __restrict__ li_nb,
                      const float* __restrict__ ra_nw, const float* __restrict__ ra_nb)
{
    __shared__ float4 sb4[8][32][2];    // [wid][chan][half] -> 8 points per channel
    int lane = threadIdx.x & 31, wid = threadIdx.x >> 5;
    int grp = blockIdx.x * 8 + wid;
    if (grp >= GRP8) return;
    int set = grp / GRP8D;                    // 0..1
    int rem = grp - set * GRP8D;
    int b = rem / (NN/8);
    int j0 = (rem - b * (NN/8)) * 8;

    const float* feat = (set ? ra_f : li_f) + (size_t)(b*NN + j0) * 32;
    float nw = (set ? ra_nw : li_nw)[lane];
    float nbv = (set ? ra_nb : li_nb)[lane];

    // front-batched loads (MLP=8)
    float x[8];
    #pragma unroll
    for (int p = 0; p < 8; p++) x[p] = feat[p*32 + lane];

    float* sbf = (float*)&sb4[wid][lane][0];
    #pragma unroll
    for (int p = 0; p < 8; p++) {
        float s = x[p];
        #pragma unroll
        for (int o = 16; o; o >>= 1) s += __shfl_xor_sync(~0u, s, o);
        float mu = s * (1.f/32.f);
        float dx = x[p] - mu;
        float vv = dx * dx;
        #pragma unroll
        for (int o = 16; o; o >>= 1) vv += __shfl_xor_sync(~0u, vv, o);
        sbf[p] = dx * rsqrtf(vv * (1.f/32.f) + 1e-5f) * nw + nbv;
    }
    __syncwarp();

    int dq = set, dk = set ^ 1;
    float aq[8], ak[8], av[8];
    float bqv = g_bq[dq][lane], bkv = g_bkv[dk][lane], bvv = g_bv0[dk][lane];
    #pragma unroll
    for (int p = 0; p < 8; p++) { aq[p] = bqv; ak[p] = bkv; av[p] = bvv; }

    #pragma unroll 2
    for (int c = 0; c < 32; c++) {
        float wq = g_W[dq][0][c][lane];
        float wk = g_W[dk][1][c][lane];
        float wv = g_W[dk][2][c][lane];
        float4 f0 = sb4[wid][c][0];     // LDS.128, broadcast
        float4 f1 = sb4[wid][c][1];
        aq[0] = fmaf(f0.x, wq, aq[0]); aq[1] = fmaf(f0.y, wq, aq[1]);
        aq[2] = fmaf(f0.z, wq, aq[2]); aq[3] = fmaf(f0.w, wq, aq[3]);
        aq[4] = fmaf(f1.x, wq, aq[4]); aq[5] = fmaf(f1.y, wq, aq[5]);
        aq[6] = fmaf(f1.z, wq, aq[6]); aq[7] = fmaf(f1.w, wq, aq[7]);
        ak[0] = fmaf(f0.x, wk, ak[0]); ak[1] = fmaf(f0.y, wk, ak[1]);
        ak[2] = fmaf(f0.z, wk, ak[2]); ak[3] = fmaf(f0.w, wk, ak[3]);
        ak[4] = fmaf(f1.x, wk, ak[4]); ak[5] = fmaf(f1.y, wk, ak[5]);
        ak[6] = fmaf(f1.z, wk, ak[6]); ak[7] = fmaf(f1.w, wk, ak[7]);
        av[0] = fmaf(f0.x, wv, av[0]); av[1] = fmaf(f0.y, wv, av[1]);
        av[2] = fmaf(f0.z, wv, av[2]); av[3] = fmaf(f0.w, wv, av[3]);
        av[4] = fmaf(f1.x, wv, av[4]); av[5] = fmaf(f1.y, wv, av[5]);
        av[6] = fmaf(f1.z, wv, av[6]); av[7] = fmaf(f1.w, wv, av[7]);
    }

    size_t pq = ((size_t)(dq*BB + b) * NN + j0);
    size_t pk = ((size_t)(dk*BB + b) * NN + j0);
    float bki = g_bkinv[dq][lane];
    #pragma unroll
    for (int p = 0; p < 8; p++) {
        g_q[(pq+p)*32 + lane] = aq[p];
        g_k[(pk+p)*32 + lane] = ak[p];
        g_v[(pk+p)*32 + lane] = av[p];
        // invalid-neighbor score: dot(q, bk_inv)/4 per head
        float pr = aq[p] * bki;
        pr += __shfl_xor_sync(~0u, pr, 8);
        pr += __shfl_xor_sync(~0u, pr, 4);
        pr += __shfl_xor_sync(~0u, pr, 2);
        pr += __shfl_xor_sync(~0u, pr, 1);
        if ((lane & 15) == 0) g_sinv[(pq+p)*2 + (lane >> 4)] = pr * 0.25f;
    }

    if (lane < 8) {
        const int2* cc = (const int2*)((set ? ra_c : li_c) + (size_t)(b*NN + j0) * 2);
        int2 hw = __ldg(&cc[lane]);
        g_lut[(dk*BB + b) * HWSZ + hw.x*WW + hw.y] = (unsigned short)(j0 + lane);
    }
}

// ---------------- K4: sparse attention, 4 points per warp, both directions -------
__global__ void k_attn(const int* __restrict__ li_c, const int* __restrict__ ra_c)
{
    __shared__ float4 sb4[8][32];
    int lane = threadIdx.x & 31, wid = threadIdx.x >> 5;
    int grp = blockIdx.x * 8 + wid;
    if (grp >= GRPS) return;
    int d = grp / GRPD;
    int rem = grp - d * GRPD;
    int b = rem / (NN/4);
    int j0 = (rem - b * (NN/4)) * 4;

    size_t base = (size_t)(d*BB + b) * NN + j0;     // q / o / sinv rows
    size_t kvbase = (size_t)(d*BB + b) * NN;        // kv pool (other modality)
    const unsigned short* lut = g_lut + (d*BB + b) * HWSZ;

    const int* qc = (d == 0 ? li_c : ra_c) + (size_t)(b*NN + j0) * 2;
    int craw = (lane < 8) ? __ldg(&qc[lane]) : 0;

    int head = lane >> 4;

    // front-batched independent loads (MLP=8)
    float qv[4], siv[4];
    #pragma unroll
    for (int p = 0; p < 4; p++) qv[p] = g_q[(base+p)*32 + lane];
    #pragma unroll
    for (int p = 0; p < 4; p++) siv[p] = g_sinv[(base+p)*2 + head];

    float bvi = g_bvinv[d][lane];
    int sh_dh = (lane < 9) ? c_sh[lane][0] : 0;
    int sh_dw = (lane < 9) ? c_sh[lane][1] : 0;

    float* sbf = (float*)&sb4[wid][lane];
    #pragma unroll
    for (int p = 0; p < 4; p++) {
        int h = __shfl_sync(~0u, craw, 2*p);
        int w = __shfl_sync(~0u, craw, 2*p + 1);

        // lane-parallel probe: lane s<9 checks shift s
        int idx = -1;
        if (lane < 9) {
            int sh = h + sh_dh, sw = w + sh_dw;
            if ((unsigned)sh < (unsigned)HH && (unsigned)sw < (unsigned)WW) {
                unsigned v = __ldg(&lut[sh*WW + sw]);
                idx = (v == 0xFFFFu) ? -1 : (int)v;
            }
        }
        unsigned vm = __ballot_sync(~0u, idx >= 0);
        int nval = __popc(vm);

        // online softmax seeded with invalid class (9-nval copies of score sinv)
        float m_run = siv[p];
        float ssum = (float)(9 - nval);
        float o = ssum * bvi;

        unsigned mm = vm;
        while (mm) {
            int s = __ffs(mm) - 1; mm &= mm - 1;
            int id = __shfl_sync(~0u, idx, s);
            size_t off = (kvbase + id) * 32 + lane;
            float kc = g_k[off];
            float pr = qv[p] * kc;
            pr += __shfl_xor_sync(~0u, pr, 8);
            pr += __shfl_xor_sync(~0u, pr, 4);
            pr += __shfl_xor_sync(~0u, pr, 2);
            pr += __shfl_xor_sync(~0u, pr, 1);
            pr *= 0.25f;
            float vval = g_v[off] + g_pv[d][s][lane];
            float mnew = fmaxf(m_run, pr);
            float corr = __expf(m_run - mnew);
            float wgt  = __expf(pr - mnew);
            ssum = ssum * corr + wgt;
            o = fmaf(o, corr, wgt * vval);
            m_run = mnew;
        }
        sbf[p] = o / ssum;
    }
    __syncwarp();

    // out-projection, weights + LDS.128 reused across 4 points
    float acc[4];
    float bo = g_bo[d][lane];
    #pragma unroll
    for (int p = 0; p < 4; p++) acc[p] = bo;
    #pragma unroll 4
    for (int c = 0; c < 32; c++) {
        float wo = g_W[d][3][c][lane];
        float4 f = sb4[wid][c];         // one LDS.128, broadcast
        acc[0] = fmaf(f.x, wo, acc[0]);
        acc[1] = fmaf(f.y, wo, acc[1]);
        acc[2] = fmaf(f.z, wo, acc[2]);
        acc[3] = fmaf(f.w, wo, acc[3]);
    }
    #pragma unroll
    for (int p = 0; p < 4; p++)
        g_o[(base+p)*32 + lane] = acc[p];
}

// ---------------- K5: fused canvas zero + scatter (canvas-major, coalesced) ------
__global__ void k_scatter(float* __restrict__ out)
{
    int pix = blockIdx.x * blockDim.x + threadIdx.x;
    if (pix >= HWSZ) return;
    int db = blockIdx.y;
    int d = db >> 2, b = db & 3;

    // query coords of direction d live in lut slot ((d^1)*BB + b)
    unsigned v = __ldg(&g_lut[((d ^ 1)*BB + b) * HWSZ + pix]);
    int idx = (v == 0xFFFFu) ? -1 : (int)v;
    const float4* src = (const float4*)(g_o + ((size_t)db * NN + (idx < 0 ? 0 : idx)) * 32);
    float* dst = out + ((size_t)db * 32) * HWSZ + pix;

    #pragma unroll
    for (int c4 = 0; c4 < 8; c4++) {
        float4 vv = make_float4(0.f, 0.f, 0.f, 0.f);
        if (idx >= 0) vv = __ldg(&src[c4]);
        dst[(c4*4 + 0) * HWSZ] = vv.x;
        dst[(c4*4 + 1) * HWSZ] = vv.y;
        dst[(c4*4 + 2) * HWSZ] = vv.z;
        dst[(c4*4 + 3) * HWSZ] = vv.w;
    }
}

// --------------------------------- launch ---------------------------------------
extern "C" void kernel_launch(void* const* d_in, const int* in_sizes, int n_in,
                              void* d_out, int out_size)
{
    const float* li_f  = (const float*)d_in[0];
    const float* ra_f  = (const float*)d_in[1];
    const int*   li_c  = (const int*)d_in[2];
    const int*   ra_c  = (const int*)d_in[3];
    const float* li_nw = (const float*)d_in[4];
    const float* li_nb = (const float*)d_in[5];
    const float* ra_nw = (const float*)d_in[6];
    const float* ra_nb = (const float*)d_in[7];
    const float* qw1   = (const float*)d_in[8];
    const float* qb1   = (const float*)d_in[9];
    const float* qw2   = (const float*)d_in[10];
    const float* qb2   = (const float*)d_in[11];
    const float* posw  = (const float*)d_in[12];
    const float* posb  = (const float*)d_in[13];
    const float* iw1   = (const float*)d_in[14];
    const float* ib1   = (const float*)d_in[15];
    const float* ow1   = (const float*)d_in[16];
    const float* ob1   = (const float*)d_in[17];
    const float* iw2   = (const float*)d_in[18];
    const float* ib2   = (const float*)d_in[19];
    const float* ow2   = (const float*)d_in[20];
    const float* ob2   = (const float*)d_in[21];

    k_init<<<LUTB + 8, 1024>>>(qw1, qb1, qw2, qb2, posw, posb,
                               iw1, ib1, ow1, ob1, iw2, ib2, ow2, ob2);

    k_pre<<<(GRP8 + 7)/8, 256>>>(li_f, ra_f, li_c, ra_c, li_nw, li_nb, ra_nw, ra_nb);

    k_attn<<<(GRPS + 7)/8, 256>>>(li_c, ra_c);

    k_scatter<<<dim3((HWSZ + 255)/256, 2*BB), 256>>>((float*)d_out);
}